// round 1
// baseline (speedup 1.0000x reference)
#include <cuda_runtime.h>
#include <cstdint>

// Problem constants
// x: (B=16, C=256, W=64, P=128) fp32
// codebooks: (ns=4, K=256, sc=64) fp32
// N = B*W*P = 131072 vectors per subspace.
// out: (B, C, W, P) fp32; out[b, s*64+cc, w, p] = cb[s, idx[s, b*8192 + p*64 + w], cc]
// where idx[s, n] = argmin_k (|c_k|^2 - 2 * x_n . c_k), n = b*8192 + w_in*128 + p_in.

#define NS 4
#define KCODES 256
#define SC 64
#define NVEC 131072           // B*W*P
#define XB_STRIDE 2097152     // 256*64*128 floats per batch
#define CH_STRIDE 8192        // 64*128 floats per channel

// scratch (device globals: allowed; no allocation)
__device__ int   g_idx[NS * NVEC];
__device__ float g_c2[NS * KCODES];

// ---------------------------------------------------------------------------
// packed f32x2 helpers (Blackwell FFMA2)
// ---------------------------------------------------------------------------
__device__ __forceinline__ unsigned long long pack_f32x2(float lo, float hi) {
    unsigned long long r;
    asm("mov.b64 %0, {%1, %2};" : "=l"(r) : "f"(lo), "f"(hi));
    return r;
}
__device__ __forceinline__ unsigned long long ffma2(unsigned long long a,
                                                    unsigned long long b,
                                                    unsigned long long c) {
    unsigned long long d;
    asm("fma.rn.f32x2 %0, %1, %2, %3;" : "=l"(d) : "l"(a), "l"(b), "l"(c));
    return d;
}
__device__ __forceinline__ void unpack_f32x2(unsigned long long v, float& lo, float& hi) {
    asm("mov.b64 {%0, %1}, %2;" : "=f"(lo), "=f"(hi) : "l"(v));
}

// ---------------------------------------------------------------------------
// Kernel C2: |c_k|^2 per (s, k). 1024 rows total.
// ---------------------------------------------------------------------------
__global__ void kC2(const float* __restrict__ cb) {
    int i = blockIdx.x * 256 + threadIdx.x;   // s*256 + k, launch <<<4,256>>>
    const float* r = cb + (size_t)i * SC;
    float acc = 0.0f;
#pragma unroll
    for (int c = 0; c < SC; c++) acc = fmaf(r[c], r[c], acc);
    g_c2[i] = acc;
}

// ---------------------------------------------------------------------------
// Kernel A: argmin per (s, n). 1 thread = 1 vector.
// Codebook processed in two 128-row phases through 32 KB static smem.
// ---------------------------------------------------------------------------
__global__ __launch_bounds__(256, 2) void kA(const float* __restrict__ x,
                                             const float* __restrict__ cb) {
    __shared__ __align__(16) float cbs[128 * SC];   // 32 KB
    __shared__ float c2s[128];

    const int s = blockIdx.y;
    const int n = blockIdx.x * 256 + threadIdx.x;   // gridDim.x = 512
    const int b = n >> 13;
    const int m = n & 8191;

    // Load this thread's vector (64 floats, channel-strided; coalesced across warp)
    const float* xp = x + (size_t)b * XB_STRIDE + (size_t)(s * SC) * CH_STRIDE + m;
    unsigned long long xr[SC / 2];
#pragma unroll
    for (int j = 0; j < SC / 2; j++) {
        float lo = xp[(size_t)(2 * j) * CH_STRIDE];
        float hi = xp[(size_t)(2 * j + 1) * CH_STRIDE];
        xr[j] = pack_f32x2(lo, hi);
    }

    float best = 3.4e38f;
    int   bi   = 0;

    for (int ph = 0; ph < 2; ph++) {
        __syncthreads();
        // cooperative load of 128 codebook rows (8192 floats) as float4
        {
            const float4* src = (const float4*)(cb + (size_t)s * KCODES * SC
                                                   + (size_t)ph * 128 * SC);
            float4* dst = (float4*)cbs;
#pragma unroll
            for (int r = 0; r < 8; r++)
                dst[r * 256 + threadIdx.x] = src[r * 256 + threadIdx.x];
            if (threadIdx.x < 128)
                c2s[threadIdx.x] = g_c2[s * KCODES + ph * 128 + threadIdx.x];
        }
        __syncthreads();

        for (int k = 0; k < 128; k++) {
            const ulonglong2* row = (const ulonglong2*)(cbs + k * SC);
            unsigned long long a0 = 0ull, a1 = 0ull;   // two independent chains
#pragma unroll
            for (int j = 0; j < 16; j++) {
                ulonglong2 v = row[j];                 // broadcast LDS.128
                a0 = ffma2(xr[2 * j],     v.x, a0);
                a1 = ffma2(xr[2 * j + 1], v.y, a1);
            }
            float l0, h0, l1, h1;
            unpack_f32x2(a0, l0, h0);
            unpack_f32x2(a1, l1, h1);
            float dot = (l0 + h0) + (l1 + h1);
            float sc  = fmaf(-2.0f, dot, c2s[k]);
            if (sc < best) { best = sc; bi = ph * 128 + k; }   // first-min tie rule
        }
    }
    g_idx[s * NVEC + n] = bi;
}

// ---------------------------------------------------------------------------
// Kernel B: build output via smem gather.
// Block = (s, b, cq (16-channel quarter), pblk (64 p_o)).  512 blocks.
// out[b, s*64 + cq*16 + c, w_o, p_o] = cb[s][ idx[s, b*8192 + p_o*64 + w_o] ][cq*16+c]
// ---------------------------------------------------------------------------
__global__ __launch_bounds__(256) void kB(const float* __restrict__ cb,
                                          float* __restrict__ out) {
    __shared__ float cbq[KCODES * 17];   // 256 rows x 16 cols, padded to 17
    __shared__ int   idxt[64 * 66];      // [w_o][p_rel], padded

    const int bid  = blockIdx.x;         // 0..511
    const int pblk = bid & 1;
    const int cq   = (bid >> 1) & 3;
    const int b    = (bid >> 3) & 15;
    const int s    = bid >> 7;
    const int t    = threadIdx.x;

    // load codebook quarter (16 channels of all 256 rows)
    {
        const float4* src = (const float4*)(cb + (size_t)s * KCODES * SC + (size_t)t * SC
                                               + cq * 16);
        // thread t handles row k = t
#pragma unroll
        for (int c4 = 0; c4 < 4; c4++) {
            float4 v = src[c4];
            cbq[t * 17 + c4 * 4 + 0] = v.x;
            cbq[t * 17 + c4 * 4 + 1] = v.y;
            cbq[t * 17 + c4 * 4 + 2] = v.z;
            cbq[t * 17 + c4 * 4 + 3] = v.w;
        }
    }
    // load idx tile (4096 consecutive entries), store transposed [w_o][p_rel]
    {
        const int* src = g_idx + (size_t)s * NVEC + (size_t)b * 8192 + pblk * 4096;
#pragma unroll
        for (int r = 0; r < 16; r++) {
            int i  = r * 256 + t;          // i = p_rel*64 + w_o
            int id = src[i];
            idxt[(i & 63) * 66 + (i >> 6)] = id;
        }
    }
    __syncthreads();

    const int lane = t & 31;
    const int warp = t >> 5;

    for (int w_o = warp; w_o < 64; w_o += 8) {
        int k0 = idxt[w_o * 66 + 2 * lane];
        int k1 = idxt[w_o * 66 + 2 * lane + 1];
        const float* r0 = cbq + k0 * 17;
        const float* r1 = cbq + k1 * 17;
        float* op = out + ((((size_t)b * 256 + s * 64 + cq * 16) * 64 + w_o) * 128)
                        + pblk * 64 + 2 * lane;
#pragma unroll
        for (int c = 0; c < 16; c++) {
            float2 v;
            v.x = r0[c];
            v.y = r1[c];
            *(float2*)(op + (size_t)c * CH_STRIDE) = v;
        }
    }
}

// ---------------------------------------------------------------------------
extern "C" void kernel_launch(void* const* d_in, const int* in_sizes, int n_in,
                              void* d_out, int out_size) {
    const float* x  = (const float*)d_in[0];   // 33554432 fp32
    const float* cb = (const float*)d_in[1];   // 65536 fp32
    float* out = (float*)d_out;                // 33554432 fp32

    kC2<<<4, 256>>>(cb);
    dim3 ga(512, 4);
    kA<<<ga, 256>>>(x, cb);
    kB<<<512, 256>>>(cb, out);
}